// round 1
// baseline (speedup 1.0000x reference)
#include <cuda_runtime.h>
#include <cfloat>
#include <math.h>

#define NB 4
#define NP 8192
#define NC 64
#define NK 16
#define NTOT (NB*NP)          // 32768
#define NEG_SLOPE 0.2f
#define EPS_LN 1e-5f

// ---------------- scratch (device globals; no cudaMalloc allowed) ----------------
__device__ float g_norms[NTOT];
__device__ float g_u[NTOT*NC];      // x @ (W1 - W2) + b
__device__ float g_v[NTOT*NC];      // x @ W2
__device__ int   g_idx[NTOT*NK];    // global neighbor indices
__device__ float g_partial[256*128];// per-block [sum(64), sumsq(64)]
__device__ float g_ss[128];         // scale(64), shift(64)

// ---------------- kernel 1: projections u, v and squared norms ----------------
// 256 threads = 8 warps, one row per warp; 4096 blocks.
__global__ void proj_kernel(const float* __restrict__ x,
                            const float* __restrict__ W,
                            const float* __restrict__ bvec) {
    __shared__ float sx[8][NC];
    int warp = threadIdx.x >> 5, lane = threadIdx.x & 31;
    int row = blockIdx.x * 8 + warp;

    float x0 = x[row*NC + lane];
    float x1 = x[row*NC + 32 + lane];
    sx[warp][lane] = x0;
    sx[warp][lane+32] = x1;

    float nrm = x0*x0 + x1*x1;
    #pragma unroll
    for (int off = 16; off; off >>= 1) nrm += __shfl_xor_sync(0xFFFFFFFFu, nrm, off);
    if (lane == 0) g_norms[row] = nrm;
    __syncwarp();

    int o0 = lane, o1 = lane + 32;
    float au0 = bvec[o0], au1 = bvec[o1];
    float av0 = 0.f, av1 = 0.f;
    #pragma unroll
    for (int c = 0; c < NC; c++) {
        float xc = sx[warp][c];
        float w1a = W[c*NC + o0];
        float w1b = W[c*NC + o1];
        float w2a = W[(NC + c)*NC + o0];
        float w2b = W[(NC + c)*NC + o1];
        au0 = fmaf(xc, w1a - w2a, au0);
        au1 = fmaf(xc, w1b - w2b, au1);
        av0 = fmaf(xc, w2a, av0);
        av1 = fmaf(xc, w2b, av1);
    }
    g_u[row*NC + o0] = au0;  g_u[row*NC + o1] = au1;
    g_v[row*NC + o0] = av0;  g_v[row*NC + o1] = av1;
}

// ---------------- kernel 2: brute-force KNN (top-16 smallest distances) ----------------
__device__ __forceinline__ void knn_insert(float s, int j,
                                           float* bd, int* bi,
                                           float& cm, int& cp) {
    if (s < cm) {                  // strict <  -> earlier (smaller) index wins on ties
        bd[cp] = s; bi[cp] = j;
        float m = bd[0]; int mp = 0;
        #pragma unroll
        for (int k = 1; k < NK; k++) {
            if (bd[k] > m) { m = bd[k]; mp = k; }
        }
        cm = m; cp = mp;
    }
}

// 128 threads/block, 1 query per thread; grid = NB * (NP/128) = 256 blocks.
__global__ void knn_kernel(const float* __restrict__ x) {
    __shared__ float tile[128*NC];
    __shared__ float tnorm[128];

    int b  = blockIdx.x >> 6;                 // 64 blocks per batch
    int qi = ((blockIdx.x & 63) << 7) + threadIdx.x;   // 0..8191 within batch
    const float* xb = x + (size_t)b * NP * NC;

    // query in registers
    float q[NC];
    #pragma unroll
    for (int c = 0; c < NC; c += 4) {
        float4 t = *(const float4*)(xb + (size_t)qi*NC + c);
        q[c] = t.x; q[c+1] = t.y; q[c+2] = t.z; q[c+3] = t.w;
    }

    float bestd[NK]; int besti[NK];
    #pragma unroll
    for (int k = 0; k < NK; k++) { bestd[k] = FLT_MAX; besti[k] = 0; }
    float curmax = FLT_MAX; int maxpos = 0;

    for (int jt = 0; jt < NP; jt += 128) {
        __syncthreads();
        const float4* src = (const float4*)(xb + (size_t)jt*NC);
        float4* dst = (float4*)tile;
        #pragma unroll
        for (int t = threadIdx.x; t < 128*NC/4; t += 128) dst[t] = src[t];
        tnorm[threadIdx.x] = g_norms[b*NP + jt + threadIdx.x];
        __syncthreads();

        for (int j = 0; j < 128; j += 4) {
            float a0 = 0.f, a1 = 0.f, a2 = 0.f, a3 = 0.f;
            #pragma unroll
            for (int c = 0; c < NC; c += 4) {
                float4 c0 = *(const float4*)&tile[(j+0)*NC + c];
                float4 c1 = *(const float4*)&tile[(j+1)*NC + c];
                float4 c2 = *(const float4*)&tile[(j+2)*NC + c];
                float4 c3 = *(const float4*)&tile[(j+3)*NC + c];
                a0 = fmaf(q[c], c0.x, a0); a0 = fmaf(q[c+1], c0.y, a0);
                a0 = fmaf(q[c+2], c0.z, a0); a0 = fmaf(q[c+3], c0.w, a0);
                a1 = fmaf(q[c], c1.x, a1); a1 = fmaf(q[c+1], c1.y, a1);
                a1 = fmaf(q[c+2], c1.z, a1); a1 = fmaf(q[c+3], c1.w, a1);
                a2 = fmaf(q[c], c2.x, a2); a2 = fmaf(q[c+1], c2.y, a2);
                a2 = fmaf(q[c+2], c2.z, a2); a2 = fmaf(q[c+3], c2.w, a2);
                a3 = fmaf(q[c], c3.x, a3); a3 = fmaf(q[c+1], c3.y, a3);
                a3 = fmaf(q[c+2], c3.z, a3); a3 = fmaf(q[c+3], c3.w, a3);
            }
            float s0 = tnorm[j+0] - 2.f*a0;
            float s1 = tnorm[j+1] - 2.f*a1;
            float s2 = tnorm[j+2] - 2.f*a2;
            float s3 = tnorm[j+3] - 2.f*a3;
            int jg = b*NP + jt + j;
            knn_insert(s0, jg+0, bestd, besti, curmax, maxpos);
            knn_insert(s1, jg+1, bestd, besti, curmax, maxpos);
            knn_insert(s2, jg+2, bestd, besti, curmax, maxpos);
            knn_insert(s3, jg+3, bestd, besti, curmax, maxpos);
        }
    }

    int gq = b*NP + qi;
    #pragma unroll
    for (int k = 0; k < NK; k++) g_idx[gq*NK + k] = besti[k];
}

// ---------------- kernel 3: per-channel sum / sumsq (partials, deterministic) ----------------
// 256 blocks x 256 threads (8 warps); warp owns strided point set; lane owns ch {lane, lane+32}.
__global__ void stats_kernel() {
    __shared__ float red_s[8][NC];
    __shared__ float red_q[8][NC];
    int warp = threadIdx.x >> 5, lane = threadIdx.x & 31;
    int gw = blockIdx.x * 8 + warp;     // 0..2047

    float s10 = 0.f, s11 = 0.f, s20 = 0.f, s21 = 0.f;
    for (int i = gw; i < NTOT; i += 2048) {
        const float* up = g_u + (size_t)i*NC;
        float u0 = up[lane], u1 = up[lane+32];
        const int* ip = g_idx + (size_t)i*NK;
        #pragma unroll
        for (int k = 0; k < NK; k++) {
            int j = ip[k];
            const float* vp = g_v + (size_t)j*NC;
            float h0 = u0 + vp[lane];
            float h1 = u1 + vp[lane+32];
            s10 += h0; s20 = fmaf(h0, h0, s20);
            s11 += h1; s21 = fmaf(h1, h1, s21);
        }
    }
    red_s[warp][lane] = s10;  red_s[warp][lane+32] = s11;
    red_q[warp][lane] = s20;  red_q[warp][lane+32] = s21;
    __syncthreads();
    if (threadIdx.x < NC) {
        float ts = 0.f, tq = 0.f;
        #pragma unroll
        for (int w = 0; w < 8; w++) { ts += red_s[w][threadIdx.x]; tq += red_q[w][threadIdx.x]; }
        g_partial[blockIdx.x*128 + threadIdx.x]      = ts;
        g_partial[blockIdx.x*128 + 64 + threadIdx.x] = tq;
    }
}

// ---------------- kernel 4: final reduction -> scale/shift ----------------
__global__ void reduce_kernel(const float* __restrict__ gamma,
                              const float* __restrict__ beta) {
    int t = threadIdx.x;   // 128 threads
    float s = 0.f;
    for (int blk = 0; blk < 256; blk++) s += g_partial[blk*128 + t];
    __shared__ float tot[128];
    tot[t] = s;
    __syncthreads();
    if (t < NC) {
        double N    = (double)NTOT * (double)NK;   // 524288
        double mean = (double)tot[t] / N;
        double msq  = (double)tot[64 + t] / N;
        double var  = msq - mean*mean;
        double inv  = 1.0 / sqrt(var + (double)EPS_LN);
        double sc   = (double)gamma[t] * inv;
        g_ss[t]      = (float)sc;
        g_ss[64 + t] = (float)((double)beta[t] - mean*sc);
    }
}

// ---------------- kernel 5: normalize + leaky-relu + max over K ----------------
__global__ void out_kernel(float* __restrict__ out) {
    int warp = threadIdx.x >> 5, lane = threadIdx.x & 31;
    int gw = blockIdx.x * 8 + warp;
    float sc0 = g_ss[lane],      sc1 = g_ss[lane+32];
    float sh0 = g_ss[64 + lane], sh1 = g_ss[96 + lane];

    for (int i = gw; i < NTOT; i += 2048) {
        const float* up = g_u + (size_t)i*NC;
        float u0 = up[lane], u1 = up[lane+32];
        const int* ip = g_idx + (size_t)i*NK;
        float m0 = -FLT_MAX, m1 = -FLT_MAX;
        #pragma unroll
        for (int k = 0; k < NK; k++) {
            int j = ip[k];
            const float* vp = g_v + (size_t)j*NC;
            float h0 = u0 + vp[lane];
            float h1 = u1 + vp[lane+32];
            float n0 = fmaf(h0, sc0, sh0);
            float n1 = fmaf(h1, sc1, sh1);
            float a0 = (n0 >= 0.f) ? n0 : NEG_SLOPE*n0;
            float a1 = (n1 >= 0.f) ? n1 : NEG_SLOPE*n1;
            m0 = fmaxf(m0, a0);
            m1 = fmaxf(m1, a1);
        }
        out[(size_t)i*NC + lane]      = m0;
        out[(size_t)i*NC + lane+32]   = m1;
    }
}

// ---------------- launch ----------------
extern "C" void kernel_launch(void* const* d_in, const int* in_sizes, int n_in,
                              void* d_out, int out_size) {
    const float* x     = (const float*)d_in[0];
    // d_in[1] = batch (int64) — structure is fixed (P points per batch), unused
    const float* W     = (const float*)d_in[2];
    const float* bvec  = (const float*)d_in[3];
    const float* gamma = (const float*)d_in[4];
    const float* beta  = (const float*)d_in[5];
    float* out = (float*)d_out;

    proj_kernel<<<NTOT/8, 256>>>(x, W, bvec);
    knn_kernel<<<NB*(NP/128), 128>>>(x);
    stats_kernel<<<256, 256>>>();
    reduce_kernel<<<1, 128>>>(gamma, beta);
    out_kernel<<<256, 256>>>(out);
}